// round 12
// baseline (speedup 1.0000x reference)
#include <cuda_runtime.h>
#include <cuda_bf16.h>
#include <cstdint>
#include <cstddef>

#define NN 50000
#define EE 1250000
#define LF 64
#define HF 128
#define EPSV 1e-6f
#define NB_SCAN 196   // ceil(50000/256)

// ---------------- static device scratch (no allocs allowed) ----------------
__device__ float g_e[(size_t)EE * LF];                 // edge latents (CSR order)
__device__ float g_n[(size_t)(NN + 128) * LF];         // node latents (padded)
__device__ __nv_bfloat16 g_xh[(size_t)(NN + 128) * LF];// processor input hi (padded)
__device__ __nv_bfloat16 g_xl[(size_t)(NN + 128) * LF];// processor input lo (padded)
__device__ __nv_bfloat16 g_wt[22 * 32768];             // weights: [N][K] bf16, hi then lo(+16384)
__device__ int g_deg[NN];
__device__ int g_off[NN + 1];
__device__ int g_cur[NN];
__device__ int g_bsum[NB_SCAN];
__device__ int g_slot[EE];
__device__ int g_sperm[EE];

// ---------------- CSR build ----------------
__global__ void k_hist(const int* __restrict__ recv) {
    int i = blockIdx.x * blockDim.x + threadIdx.x;
    if (i < EE) atomicAdd(&g_deg[recv[i]], 1);
}

__global__ void k_scan1() {
    __shared__ int sh[256];
    int t = threadIdx.x;
    int i = blockIdx.x * 256 + t;
    int v = (i < NN) ? g_deg[i] : 0;
    sh[t] = v;
    __syncthreads();
#pragma unroll
    for (int d = 1; d < 256; d <<= 1) {
        int x = (t >= d) ? sh[t - d] : 0;
        __syncthreads();
        sh[t] += x;
        __syncthreads();
    }
    if (i < NN) g_off[i] = sh[t] - v;
    if (t == 255) g_bsum[blockIdx.x] = sh[255];
}

__global__ void k_scan2() {
    __shared__ int sh[256];
    int t = threadIdx.x;
    int v = (t < NB_SCAN) ? g_bsum[t] : 0;
    sh[t] = v;
    __syncthreads();
#pragma unroll
    for (int d = 1; d < 256; d <<= 1) {
        int x = (t >= d) ? sh[t - d] : 0;
        __syncthreads();
        sh[t] += x;
        __syncthreads();
    }
    if (t < NB_SCAN) g_bsum[t] = sh[t] - v;
}

__global__ void k_scan3() {
    int i = blockIdx.x * 256 + threadIdx.x;
    if (i < NN) {
        int o = g_off[i] + g_bsum[blockIdx.x];
        g_off[i] = o;
        g_cur[i] = o;
    }
    if (i == 0) g_off[NN] = EE;
}

__global__ void k_scatter(const int* __restrict__ recv, const int* __restrict__ send) {
    int i = blockIdx.x * blockDim.x + threadIdx.x;
    if (i < EE) {
        int p = atomicAdd(&g_cur[recv[i]], 1);
        g_slot[i] = p;
        g_sperm[p] = send[i];
    }
}

// ---------------- weight prep: fp32 [K][N] -> bf16 hi/lo [N][K] ----------------
struct WSlot { const float* src; int N; int K; };
struct WTable { WSlot s[22]; };

__global__ void k_prep(WTable tab) {
    int m = blockIdx.y;
    WSlot sl = tab.s[m];
    int total = sl.N * sl.K;
    int e = blockIdx.x * 256 + threadIdx.x;
    if (e >= total) return;
    int k = e / sl.N;
    int n = e - k * sl.N;
    float v = __ldg(&sl.src[e]);
    __nv_bfloat16 h = __float2bfloat16(v);
    __nv_bfloat16 l = __float2bfloat16(v - __bfloat162float(h));
    size_t off = (size_t)m * 32768 + (size_t)n * sl.K + k;
    g_wt[off] = h;
    g_wt[off + 16384] = l;
}

// ---------------- softmax aggregation: 1 warp/node, 2 streams, float2 lanes ----------------
__global__ void k_agg(const float* __restrict__ n, const float* __restrict__ e,
                      const int* __restrict__ sp, const int* __restrict__ off,
                      __nv_bfloat16* __restrict__ xh, __nv_bfloat16* __restrict__ xl) {
    int w = (blockIdx.x * blockDim.x + threadIdx.x) >> 5;
    int lane = threadIdx.x & 31;
    if (w >= NN) return;
    int p0 = __ldg(&off[w]);
    int p1 = __ldg(&off[w + 1]);
    const int f2 = lane * 2;  // features f2, f2+1

    const float NEG = -3.0e38f;
    float mxA0 = NEG, mxA1 = NEG, mxB0 = NEG, mxB1 = NEG;
    float saA0 = 0.f, sbA0 = 0.f, saA1 = 0.f, sbA1 = 0.f;
    float saB0 = 0.f, sbB0 = 0.f, saB1 = 0.f, sbB1 = 0.f;

    int p = p0;
    for (; p + 1 < p1; p += 2) {
        int sA = __ldg(&sp[p]);
        int sB = __ldg(&sp[p + 1]);
        float2 evA = *(const float2*)(e + (size_t)p * LF + f2);
        float2 evB = *(const float2*)(e + (size_t)(p + 1) * LF + f2);
        float2 nvA = *(const float2*)(n + (size_t)sA * LF + f2);
        float2 nvB = *(const float2*)(n + (size_t)sB * LF + f2);
        float mA0 = fmaxf(nvA.x + evA.x, 0.f) + EPSV;
        float mA1 = fmaxf(nvA.y + evA.y, 0.f) + EPSV;
        float mB0 = fmaxf(nvB.x + evB.x, 0.f) + EPSV;
        float mB1 = fmaxf(nvB.y + evB.y, 0.f) + EPSV;

        float nm, c, t;
        nm = fmaxf(mxA0, mA0); c = __expf(mxA0 - nm); t = __expf(mA0 - nm);
        saA0 = saA0 * c + t; sbA0 = sbA0 * c + t * mA0; mxA0 = nm;
        nm = fmaxf(mxA1, mA1); c = __expf(mxA1 - nm); t = __expf(mA1 - nm);
        saA1 = saA1 * c + t; sbA1 = sbA1 * c + t * mA1; mxA1 = nm;
        nm = fmaxf(mxB0, mB0); c = __expf(mxB0 - nm); t = __expf(mB0 - nm);
        saB0 = saB0 * c + t; sbB0 = sbB0 * c + t * mB0; mxB0 = nm;
        nm = fmaxf(mxB1, mB1); c = __expf(mxB1 - nm); t = __expf(mB1 - nm);
        saB1 = saB1 * c + t; sbB1 = sbB1 * c + t * mB1; mxB1 = nm;
    }
    if (p < p1) {
        int sA = __ldg(&sp[p]);
        float2 evA = *(const float2*)(e + (size_t)p * LF + f2);
        float2 nvA = *(const float2*)(n + (size_t)sA * LF + f2);
        float mA0 = fmaxf(nvA.x + evA.x, 0.f) + EPSV;
        float mA1 = fmaxf(nvA.y + evA.y, 0.f) + EPSV;
        float nm, c, t;
        nm = fmaxf(mxA0, mA0); c = __expf(mxA0 - nm); t = __expf(mA0 - nm);
        saA0 = saA0 * c + t; sbA0 = sbA0 * c + t * mA0; mxA0 = nm;
        nm = fmaxf(mxA1, mA1); c = __expf(mxA1 - nm); t = __expf(mA1 - nm);
        saA1 = saA1 * c + t; sbA1 = sbA1 * c + t * mA1; mxA1 = nm;
    }

    // merge streams (finite sentinel -> no NaN)
    float nm0 = fmaxf(mxA0, mxB0);
    float cA0 = __expf(mxA0 - nm0), cB0 = __expf(mxB0 - nm0);
    float sa0 = saA0 * cA0 + saB0 * cB0;
    float sb0 = sbA0 * cA0 + sbB0 * cB0;
    float nm1 = fmaxf(mxA1, mxB1);
    float cA1 = __expf(mxA1 - nm1), cB1 = __expf(mxB1 - nm1);
    float sa1 = saA1 * cA1 + saB1 * cB1;
    float sb1 = sbA1 * cA1 + sbB1 * cB1;

    float a0 = (sa0 > 0.f) ? sb0 / sa0 : 0.f;
    float a1 = (sa1 > 0.f) ? sb1 / sa1 : 0.f;
    size_t nb = (size_t)w * LF;
    float2 nv = *(const float2*)(n + nb + f2);
    float x0 = nv.x + a0;
    float x1 = nv.y + a1;
    __nv_bfloat16 h0 = __float2bfloat16(x0);
    __nv_bfloat16 h1 = __float2bfloat16(x1);
    *(__nv_bfloat162*)(xh + nb + f2) = __nv_bfloat162(h0, h1);
    *(__nv_bfloat162*)(xl + nb + f2) = __nv_bfloat162(
        __float2bfloat16(x0 - __bfloat162float(h0)),
        __float2bfloat16(x1 - __bfloat162float(h1)));
}

// ---------------- mma.sync helpers ----------------
__device__ __forceinline__ void mma_bf16(float* c, uint32_t a0, uint32_t a1, uint32_t a2, uint32_t a3,
                                         uint32_t b0, uint32_t b1) {
    asm volatile("mma.sync.aligned.m16n8k16.row.col.f32.bf16.bf16.f32 "
                 "{%0,%1,%2,%3}, {%4,%5,%6,%7}, {%8,%9}, {%0,%1,%2,%3};"
                 : "+f"(c[0]), "+f"(c[1]), "+f"(c[2]), "+f"(c[3])
                 : "r"(a0), "r"(a1), "r"(a2), "r"(a3), "r"(b0), "r"(b1));
}

__device__ __forceinline__ void split_pack(float a, float b, uint32_t& hi, uint32_t& lo) {
    __nv_bfloat16 ha = __float2bfloat16(a), hb = __float2bfloat16(b);
    float ra = a - __bfloat162float(ha), rb = b - __bfloat162float(hb);
    hi = (uint32_t)__bfloat16_as_ushort(ha) | ((uint32_t)__bfloat16_as_ushort(hb) << 16);
    lo = (uint32_t)__bfloat16_as_ushort(__float2bfloat16(ra)) |
         ((uint32_t)__bfloat16_as_ushort(__float2bfloat16(rb)) << 16);
}

#define SP 136  // smem row stride (bf16)

template <int NT, int KST>
__device__ __forceinline__ void gemm_half(const __nv_bfloat16* Ah, const __nv_bfloat16* Al,
                                          const __nv_bfloat16* Bh, const __nv_bfloat16* Bl,
                                          int mb, int g, int tg, float (*acc)[4]) {
#pragma unroll
    for (int k = 0; k < KST; k++) {
        int k0 = k * 16 + tg * 2;
        uint32_t ah0 = *(const uint32_t*)(Ah + (mb + g) * SP + k0);
        uint32_t ah1 = *(const uint32_t*)(Ah + (mb + g + 8) * SP + k0);
        uint32_t ah2 = *(const uint32_t*)(Ah + (mb + g) * SP + k0 + 8);
        uint32_t ah3 = *(const uint32_t*)(Ah + (mb + g + 8) * SP + k0 + 8);
        uint32_t al0 = *(const uint32_t*)(Al + (mb + g) * SP + k0);
        uint32_t al1 = *(const uint32_t*)(Al + (mb + g + 8) * SP + k0);
        uint32_t al2 = *(const uint32_t*)(Al + (mb + g) * SP + k0 + 8);
        uint32_t al3 = *(const uint32_t*)(Al + (mb + g + 8) * SP + k0 + 8);
#pragma unroll
        for (int t = 0; t < NT; t++) {
            int nb = t * 8 + g;
            uint32_t bh0 = *(const uint32_t*)(Bh + nb * SP + k0);
            uint32_t bh1 = *(const uint32_t*)(Bh + nb * SP + k0 + 8);
            uint32_t bl0 = *(const uint32_t*)(Bl + nb * SP + k0);
            uint32_t bl1 = *(const uint32_t*)(Bl + nb * SP + k0 + 8);
            mma_bf16(acc[t], ah0, ah1, ah2, ah3, bh0, bh1);
            mma_bf16(acc[t], ah0, ah1, ah2, ah3, bl0, bl1);
            mma_bf16(acc[t], al0, al1, al2, al3, bh0, bh1);
        }
    }
}

template <int NT>
__device__ __forceinline__ void epi_relu_to_A(float (*acc)[4], const float* bias,
                                              __nv_bfloat16* Ah, __nv_bfloat16* Al,
                                              int mb, int g, int tg) {
    int r0 = mb + g, r1 = mb + g + 8;
#pragma unroll
    for (int t = 0; t < NT; t++) {
        int c0 = t * 8 + tg * 2;
        float b0 = __ldg(&bias[c0]), b1 = __ldg(&bias[c0 + 1]);
        uint32_t h, l;
        split_pack(fmaxf(acc[t][0] + b0, 0.f), fmaxf(acc[t][1] + b1, 0.f), h, l);
        *(uint32_t*)(Ah + r0 * SP + c0) = h;
        *(uint32_t*)(Al + r0 * SP + c0) = l;
        split_pack(fmaxf(acc[t][2] + b0, 0.f), fmaxf(acc[t][3] + b1, 0.f), h, l);
        *(uint32_t*)(Ah + r1 * SP + c0) = h;
        *(uint32_t*)(Al + r1 * SP + c0) = l;
    }
}

// ---------------- fused 3-layer MLP on tensor pipe, 2 CTAs/SM ----------------
// smem: Ah/Al [128][SP] + Bh/Bl [64][SP] bf16 = 104448 B.
template <int IN_F, int OUT_F, bool SCATTER, bool MASK, bool XSPLIT>
__global__ void __launch_bounds__(256, 2)
k_mlp3_tc(const float* __restrict__ X,
          const __nv_bfloat16* __restrict__ Xh, const __nv_bfloat16* __restrict__ Xl,
          int rows,
          const float* __restrict__ W0f, const __nv_bfloat16* __restrict__ w0t,
          const float* __restrict__ B0,
          const __nv_bfloat16* __restrict__ w1t, const float* __restrict__ B1,
          const __nv_bfloat16* __restrict__ w2t, const float* __restrict__ B2,
          float* __restrict__ out, const int* __restrict__ slot,
          const float* __restrict__ rawn) {
    extern __shared__ __nv_bfloat16 smb[];
    __nv_bfloat16* Ah = smb;
    __nv_bfloat16* Al = smb + 128 * SP;
    __nv_bfloat16* Bh = smb + 2 * 128 * SP;
    __nv_bfloat16* Bl = smb + (2 * 128 + 64) * SP;

    const int tid  = threadIdx.x;
    const int lane = tid & 31;
    const int wid  = tid >> 5;
    const int g    = lane >> 2;
    const int tg   = lane & 3;
    const int mb   = wid * 16;
    const int row0 = blockIdx.x * 128;

    float acc[16][4];

    // ================= layer 0 =================
    if (IN_F <= 4) {
        int row = tid & 127;
        int ch  = (tid >> 7) * 64;
        int gr  = row0 + row;
        float xv[IN_F];
#pragma unroll
        for (int i = 0; i < IN_F; i++)
            xv[i] = (gr < rows) ? __ldg(&X[(size_t)gr * IN_F + i]) : 0.f;
        uint32_t* ph = (uint32_t*)(Ah + row * SP + ch);
        uint32_t* pl = (uint32_t*)(Al + row * SP + ch);
#pragma unroll 4
        for (int j = 0; j < 32; j++) {
            int c = ch + 2 * j;
            float v0 = __ldg(&B0[c]), v1 = __ldg(&B0[c + 1]);
#pragma unroll
            for (int i = 0; i < IN_F; i++) {
                v0 += xv[i] * __ldg(&W0f[i * HF + c]);
                v1 += xv[i] * __ldg(&W0f[i * HF + c + 1]);
            }
            uint32_t h, l;
            split_pack(fmaxf(v0, 0.f), fmaxf(v1, 0.f), h, l);
            ph[j] = h;
            pl[j] = l;
        }
        __syncthreads();
    } else {
        if (XSPLIT) {
            const uint32_t* shp = (const uint32_t*)Xh + (size_t)row0 * 32;
            const uint32_t* slp = (const uint32_t*)Xl + (size_t)row0 * 32;
            for (int idx = tid; idx < 128 * 32; idx += 256) {
                int r = idx >> 5, w = idx & 31;
                ((uint32_t*)Ah)[r * 68 + w] = shp[idx];
                ((uint32_t*)Al)[r * 68 + w] = slp[idx];
            }
        } else {
            const float2* xs = (const float2*)(X + (size_t)row0 * 64);
            for (int idx = tid; idx < 128 * 32; idx += 256) {
                int r = idx >> 5, w = idx & 31;
                float2 v = __ldg(&xs[idx]);
                uint32_t h, l;
                split_pack(v.x, v.y, h, l);
                ((uint32_t*)Ah)[r * 68 + w] = h;
                ((uint32_t*)Al)[r * 68 + w] = l;
            }
        }
#pragma unroll
        for (int t = 0; t < 16; t++)
#pragma unroll
            for (int j = 0; j < 4; j++) acc[t][j] = 0.f;
        const uint32_t* s0 = (const uint32_t*)w0t;
#pragma unroll
        for (int nh = 0; nh < 2; nh++) {
            __syncthreads();
            for (int idx = tid; idx < 64 * 32; idx += 256) {
                int r = idx >> 5, w = idx & 31;
                ((uint32_t*)Bh)[r * 68 + w] = s0[(nh * 64 + r) * 32 + w];
                ((uint32_t*)Bl)[r * 68 + w] = s0[(nh * 64 + r) * 32 + w + 8192];
            }
            __syncthreads();
            gemm_half<8, 4>(Ah, Al, Bh, Bl, mb, g, tg, acc + nh * 8);
        }
        __syncthreads();
        epi_relu_to_A<16>(acc, B0, Ah, Al, mb, g, tg);
        __syncthreads();
    }

    // ================= layer 1 (128 -> 128), two 64-N halves =================
#pragma unroll
    for (int t = 0; t < 16; t++)
#pragma unroll
        for (int j = 0; j < 4; j++) acc[t][j] = 0.f;
    {
        const uint32_t* s1 = (const uint32_t*)w1t;
#pragma unroll
        for (int nh = 0; nh < 2; nh++) {
            if (nh) __syncthreads();
            for (int idx = tid; idx < 64 * 64; idx += 256) {
                int r = idx >> 6, w = idx & 63;
                ((uint32_t*)Bh)[r * 68 + w] = s1[(nh * 64 + r) * 64 + w];
                ((uint32_t*)Bl)[r * 68 + w] = s1[(nh * 64 + r) * 64 + w + 8192];
            }
            __syncthreads();
            gemm_half<8, 8>(Ah, Al, Bh, Bl, mb, g, tg, acc + nh * 8);
        }
    }
    __syncthreads();
    epi_relu_to_A<16>(acc, B1, Ah, Al, mb, g, tg);
    __syncthreads();

    // ================= layer 2 (128 -> OUT_F, linear) =================
    constexpr int NT2 = (OUT_F + 7) / 8;
    if (OUT_F % 8) {
        for (int idx = tid; idx < 8 * 68; idx += 256) {
            ((uint32_t*)Bh)[idx] = 0;
            ((uint32_t*)Bl)[idx] = 0;
        }
        __syncthreads();
    }
    {
        const uint32_t* s2 = (const uint32_t*)w2t;
        for (int idx = tid; idx < OUT_F * 64; idx += 256) {
            int r = idx >> 6, w = idx & 63;
            ((uint32_t*)Bh)[r * 68 + w] = s2[idx];
            ((uint32_t*)Bl)[r * 68 + w] = s2[idx + 8192];
        }
    }
    __syncthreads();
#pragma unroll
    for (int t = 0; t < NT2; t++)
#pragma unroll
        for (int j = 0; j < 4; j++) acc[t][j] = 0.f;
    gemm_half<NT2, 8>(Ah, Al, Bh, Bl, mb, g, tg, acc);

    // epilogue -> gmem
    {
        int r0g = row0 + mb + g;
        int r1g = r0g + 8;
        bool v0 = r0g < rows, v1 = r1g < rows;
        int o0 = 0, o1 = 0;
        float m0 = 1.f, m1 = 1.f;
        if (v0) {
            o0 = SCATTER ? __ldg(&slot[r0g]) : r0g;
            if (MASK)
                m0 = ((fabsf(rawn[(size_t)r0g * 2]) + fabsf(rawn[(size_t)r0g * 2 + 1])) != 0.f) ? 1.f : 0.f;
        }
        if (v1) {
            o1 = SCATTER ? __ldg(&slot[r1g]) : r1g;
            if (MASK)
                m1 = ((fabsf(rawn[(size_t)r1g * 2]) + fabsf(rawn[(size_t)r1g * 2 + 1])) != 0.f) ? 1.f : 0.f;
        }
#pragma unroll
        for (int t = 0; t < NT2; t++) {
            int c0 = t * 8 + tg * 2;
            if (c0 < OUT_F) {
                float b0 = __ldg(&B2[c0]), b1 = __ldg(&B2[c0 + 1]);
                if (v0) {
                    out[(size_t)o0 * OUT_F + c0]     = (acc[t][0] + b0) * m0;
                    out[(size_t)o0 * OUT_F + c0 + 1] = (acc[t][1] + b1) * m0;
                }
                if (v1) {
                    out[(size_t)o1 * OUT_F + c0]     = (acc[t][2] + b0) * m1;
                    out[(size_t)o1 * OUT_F + c0 + 1] = (acc[t][3] + b1) * m1;
                }
            }
        }
    }
}

static inline int ceilDiv(int a, int b) { return (a + b - 1) / b; }

extern "C" void kernel_launch(void* const* d_in, const int* in_sizes, int n_in,
                              void* d_out, int out_size) {
    (void)in_sizes; (void)n_in; (void)out_size;
    const float* nodes = (const float*)d_in[0];
    const float* edges = (const float*)d_in[1];
    const int*   send  = (const int*)d_in[2];
    const int*   recv  = (const int*)d_in[3];
    const float* enW0 = (const float*)d_in[4],  *enb0 = (const float*)d_in[5];
    const float* enW1 = (const float*)d_in[6],  *enb1 = (const float*)d_in[7];
    const float* enW2 = (const float*)d_in[8],  *enb2 = (const float*)d_in[9];
    const float* eeW0 = (const float*)d_in[10], *eeb0 = (const float*)d_in[11];
    const float* eeW1 = (const float*)d_in[12], *eeb1 = (const float*)d_in[13];
    const float* eeW2 = (const float*)d_in[14], *eeb2 = (const float*)d_in[15];
    const float* pW0  = (const float*)d_in[16], *pb0  = (const float*)d_in[17];
    const float* pW1  = (const float*)d_in[18], *pb1  = (const float*)d_in[19];
    const float* pW2  = (const float*)d_in[20], *pb2  = (const float*)d_in[21];
    const float* dW0  = (const float*)d_in[22], *db0  = (const float*)d_in[23];
    const float* dW1  = (const float*)d_in[24], *db1  = (const float*)d_in[25];
    const float* dW2  = (const float*)d_in[26], *db2  = (const float*)d_in[27];
    float* out = (float*)d_out;

    void *pe, *pn, *pxh, *pxl, *pwt, *pdeg, *poff, *psp, *pslot;
    cudaGetSymbolAddress(&pe, g_e);
    cudaGetSymbolAddress(&pn, g_n);
    cudaGetSymbolAddress(&pxh, g_xh);
    cudaGetSymbolAddress(&pxl, g_xl);
    cudaGetSymbolAddress(&pwt, g_wt);
    cudaGetSymbolAddress(&pdeg, g_deg);
    cudaGetSymbolAddress(&poff, g_off);
    cudaGetSymbolAddress(&psp, g_sperm);
    cudaGetSymbolAddress(&pslot, g_slot);
    const __nv_bfloat16* wt = (const __nv_bfloat16*)pwt;

    const int smemB = (2 * 128 + 2 * 64) * SP * 2;  // 104448
    cudaFuncSetAttribute(k_mlp3_tc<2, 64, false, false, false>, cudaFuncAttributeMaxDynamicSharedMemorySize, smemB);
    cudaFuncSetAttribute(k_mlp3_tc<3, 64, true,  false, false>, cudaFuncAttributeMaxDynamicSharedMemorySize, smemB);
    cudaFuncSetAttribute(k_mlp3_tc<64, 64, false, false, true>, cudaFuncAttributeMaxDynamicSharedMemorySize, smemB);
    cudaFuncSetAttribute(k_mlp3_tc<64, 2, false, true, false>,  cudaFuncAttributeMaxDynamicSharedMemorySize, smemB);

    // CSR build (by receiver)
    cudaMemsetAsync(pdeg, 0, NN * sizeof(int));
    k_hist<<<ceilDiv(EE, 256), 256>>>(recv);
    k_scan1<<<NB_SCAN, 256>>>();
    k_scan2<<<1, 256>>>();
    k_scan3<<<NB_SCAN, 256>>>();
    k_scatter<<<ceilDiv(EE, 256), 256>>>(recv, send);

    // weight prep
    WTable tb;
    tb.s[0] = {enW1, 128, 128};
    tb.s[1] = {enW2, 64, 128};
    tb.s[2] = {eeW1, 128, 128};
    tb.s[3] = {eeW2, 64, 128};
    for (int s = 0; s < 5; s++) {
        tb.s[4 + s]  = {pW0 + (size_t)s * 64 * 128,  128, 64};
        tb.s[9 + s]  = {pW1 + (size_t)s * 128 * 128, 128, 128};
        tb.s[14 + s] = {pW2 + (size_t)s * 128 * 64,  64, 128};
    }
    tb.s[19] = {dW0, 128, 64};
    tb.s[20] = {dW1, 128, 128};
    tb.s[21] = {dW2, 2, 128};
    k_prep<<<dim3(64, 22), 256>>>(tb);

    // encoders
    k_mlp3_tc<2, 64, false, false, false><<<ceilDiv(NN, 128), 256, smemB>>>(
        nodes, nullptr, nullptr, NN,
        enW0, wt + 0 * 32768, enb0, wt + 0 * 32768, enb1, wt + 1 * 32768, enb2,
        (float*)pn, nullptr, nullptr);
    k_mlp3_tc<3, 64, true, false, false><<<ceilDiv(EE, 128), 256, smemB>>>(
        edges, nullptr, nullptr, EE,
        eeW0, wt + 2 * 32768, eeb0, wt + 2 * 32768, eeb1, wt + 3 * 32768, eeb2,
        (float*)pe, (const int*)pslot, nullptr);

    // processor steps
    for (int s = 0; s < 5; s++) {
        k_agg<<<ceilDiv(NN * 32, 256), 256>>>(
            (const float*)pn, (const float*)pe, (const int*)psp, (const int*)poff,
            (__nv_bfloat16*)pxh, (__nv_bfloat16*)pxl);
        k_mlp3_tc<64, 64, false, false, true><<<ceilDiv(NN, 128), 256, smemB>>>(
            nullptr, (const __nv_bfloat16*)pxh, (const __nv_bfloat16*)pxl, NN,
            nullptr, wt + (size_t)(4 + s) * 32768, pb0 + (size_t)s * 128,
            wt + (size_t)(9 + s) * 32768, pb1 + (size_t)s * 128,
            wt + (size_t)(14 + s) * 32768, pb2 + (size_t)s * 64,
            (float*)pn, nullptr, nullptr);
    }

    // decoder + mask
    k_mlp3_tc<64, 2, false, true, false><<<ceilDiv(NN, 128), 256, smemB>>>(
        (const float*)pn, nullptr, nullptr, NN,
        nullptr, wt + 19 * 32768, db0, wt + 20 * 32768, db1, wt + 21 * 32768, db2,
        out, nullptr, nodes);
}

// round 14
// speedup vs baseline: 1.5036x; 1.5036x over previous
#include <cuda_runtime.h>
#include <cuda_bf16.h>
#include <cstdint>
#include <cstddef>

#define NN 50000
#define EE 1250000
#define LF 64
#define HF 128
#define EPSV 1e-6f
#define NB_SCAN 196   // ceil(50000/256)

// ---------------- static device scratch (no allocs allowed) ----------------
__device__ float g_e[(size_t)EE * LF];                 // edge latents (CSR order)
__device__ float g_n[(size_t)(NN + 128) * LF];         // node latents (padded)
__device__ __nv_bfloat16 g_xh[(size_t)(NN + 128) * LF];// processor input hi (padded)
__device__ __nv_bfloat16 g_xl[(size_t)(NN + 128) * LF];// processor input lo (padded)
__device__ __nv_bfloat16 g_wt[22 * 32768];             // weights: [N][K] bf16, hi then lo(+16384)
__device__ int g_deg[NN];
__device__ int g_off[NN + 1];
__device__ int g_cur[NN];
__device__ int g_bsum[NB_SCAN];
__device__ int g_slot[EE];
__device__ int g_sperm[EE];

// ---------------- CSR build ----------------
__global__ void k_hist(const int* __restrict__ recv) {
    int i = blockIdx.x * blockDim.x + threadIdx.x;
    if (i < EE) atomicAdd(&g_deg[recv[i]], 1);
}

__global__ void k_scan1() {
    __shared__ int sh[256];
    int t = threadIdx.x;
    int i = blockIdx.x * 256 + t;
    int v = (i < NN) ? g_deg[i] : 0;
    sh[t] = v;
    __syncthreads();
#pragma unroll
    for (int d = 1; d < 256; d <<= 1) {
        int x = (t >= d) ? sh[t - d] : 0;
        __syncthreads();
        sh[t] += x;
        __syncthreads();
    }
    if (i < NN) g_off[i] = sh[t] - v;
    if (t == 255) g_bsum[blockIdx.x] = sh[255];
}

__global__ void k_scan2() {
    __shared__ int sh[256];
    int t = threadIdx.x;
    int v = (t < NB_SCAN) ? g_bsum[t] : 0;
    sh[t] = v;
    __syncthreads();
#pragma unroll
    for (int d = 1; d < 256; d <<= 1) {
        int x = (t >= d) ? sh[t - d] : 0;
        __syncthreads();
        sh[t] += x;
        __syncthreads();
    }
    if (t < NB_SCAN) g_bsum[t] = sh[t] - v;
}

__global__ void k_scan3() {
    int i = blockIdx.x * 256 + threadIdx.x;
    if (i < NN) {
        int o = g_off[i] + g_bsum[blockIdx.x];
        g_off[i] = o;
        g_cur[i] = o;
    }
    if (i == 0) g_off[NN] = EE;
}

__global__ void k_scatter(const int* __restrict__ recv, const int* __restrict__ send) {
    int i = blockIdx.x * blockDim.x + threadIdx.x;
    if (i < EE) {
        int p = atomicAdd(&g_cur[recv[i]], 1);
        g_slot[i] = p;
        g_sperm[p] = send[i];
    }
}

// ---------------- weight prep: fp32 [K][N] -> bf16 hi/lo [N][K] ----------------
struct WSlot { const float* src; int N; int K; };
struct WTable { WSlot s[22]; };

__global__ void k_prep(WTable tab) {
    int m = blockIdx.y;
    WSlot sl = tab.s[m];
    int total = sl.N * sl.K;
    int e = blockIdx.x * 256 + threadIdx.x;
    if (e >= total) return;
    int k = e / sl.N;
    int n = e - k * sl.N;
    float v = __ldg(&sl.src[e]);
    __nv_bfloat16 h = __float2bfloat16(v);
    __nv_bfloat16 l = __float2bfloat16(v - __bfloat162float(h));
    size_t off = (size_t)m * 32768 + (size_t)n * sl.K + k;
    g_wt[off] = h;
    g_wt[off + 16384] = l;
}

// ---------------- softmax aggregation: R7 structure + sp-prefetch ----------------
__global__ void k_agg(const float* __restrict__ n, const float* __restrict__ e,
                      const int* __restrict__ sp, const int* __restrict__ off,
                      __nv_bfloat16* __restrict__ xh, __nv_bfloat16* __restrict__ xl) {
    int w = (blockIdx.x * blockDim.x + threadIdx.x) >> 5;
    int lane = threadIdx.x & 31;
    if (w >= NN) return;
    int p0 = __ldg(&off[w]);
    int p1 = __ldg(&off[w + 1]);

    const float NEG = -3.0e38f;
    float mxA0 = NEG, mxA1 = NEG, mxB0 = NEG, mxB1 = NEG;
    float saA0 = 0.f, sbA0 = 0.f, saA1 = 0.f, sbA1 = 0.f;
    float saB0 = 0.f, sbB0 = 0.f, saB1 = 0.f, sbB1 = 0.f;

    int p = p0;
    int sA = 0, sB = 0;
    if (p + 1 < p1) {
        sA = __ldg(&sp[p]);
        sB = __ldg(&sp[p + 1]);
    }
    while (p + 1 < p1) {
        int pn = p + 2;
        int sA2 = 0, sB2 = 0;
        if (pn + 1 < p1) {                 // prefetch next pair's indices
            sA2 = __ldg(&sp[pn]);
            sB2 = __ldg(&sp[pn + 1]);
        }
        size_t eA = (size_t)p * LF, eB = (size_t)(p + 1) * LF;
        size_t nA = (size_t)sA * LF, nB = (size_t)sB * LF;
        float mA0 = fmaxf(n[nA + lane]      + e[eA + lane],      0.f) + EPSV;
        float mA1 = fmaxf(n[nA + lane + 32] + e[eA + lane + 32], 0.f) + EPSV;
        float mB0 = fmaxf(n[nB + lane]      + e[eB + lane],      0.f) + EPSV;
        float mB1 = fmaxf(n[nB + lane + 32] + e[eB + lane + 32], 0.f) + EPSV;

        float nm, c, t;
        nm = fmaxf(mxA0, mA0); c = __expf(mxA0 - nm); t = __expf(mA0 - nm);
        saA0 = saA0 * c + t; sbA0 = sbA0 * c + t * mA0; mxA0 = nm;
        nm = fmaxf(mxA1, mA1); c = __expf(mxA1 - nm); t = __expf(mA1 - nm);
        saA1 = saA1 * c + t; sbA1 = sbA1 * c + t * mA1; mxA1 = nm;
        nm = fmaxf(mxB0, mB0); c = __expf(mxB0 - nm); t = __expf(mB0 - nm);
        saB0 = saB0 * c + t; sbB0 = sbB0 * c + t * mB0; mxB0 = nm;
        nm = fmaxf(mxB1, mB1); c = __expf(mxB1 - nm); t = __expf(mB1 - nm);
        saB1 = saB1 * c + t; sbB1 = sbB1 * c + t * mB1; mxB1 = nm;

        p = pn;
        sA = sA2;
        sB = sB2;
    }
    if (p < p1) {
        int sT = __ldg(&sp[p]);
        size_t eA = (size_t)p * LF, nA = (size_t)sT * LF;
        float mA0 = fmaxf(n[nA + lane]      + e[eA + lane],      0.f) + EPSV;
        float mA1 = fmaxf(n[nA + lane + 32] + e[eA + lane + 32], 0.f) + EPSV;
        float nm, c, t;
        nm = fmaxf(mxA0, mA0); c = __expf(mxA0 - nm); t = __expf(mA0 - nm);
        saA0 = saA0 * c + t; sbA0 = sbA0 * c + t * mA0; mxA0 = nm;
        nm = fmaxf(mxA1, mA1); c = __expf(mxA1 - nm); t = __expf(mA1 - nm);
        saA1 = saA1 * c + t; sbA1 = sbA1 * c + t * mA1; mxA1 = nm;
    }

    // merge streams (finite sentinel -> no NaN)
    float nm0 = fmaxf(mxA0, mxB0);
    float sa0 = saA0 * __expf(mxA0 - nm0) + saB0 * __expf(mxB0 - nm0);
    float sb0 = sbA0 * __expf(mxA0 - nm0) + sbB0 * __expf(mxB0 - nm0);
    float nm1 = fmaxf(mxA1, mxB1);
    float sa1 = saA1 * __expf(mxA1 - nm1) + saB1 * __expf(mxB1 - nm1);
    float sb1 = sbA1 * __expf(mxA1 - nm1) + sbB1 * __expf(mxB1 - nm1);

    float a0 = (sa0 > 0.f) ? sb0 / sa0 : 0.f;
    float a1 = (sa1 > 0.f) ? sb1 / sa1 : 0.f;
    size_t nb = (size_t)w * LF;
    float x0 = n[nb + lane]      + a0;
    float x1 = n[nb + lane + 32] + a1;
    __nv_bfloat16 h0 = __float2bfloat16(x0);
    __nv_bfloat16 h1 = __float2bfloat16(x1);
    xh[nb + lane]      = h0;
    xl[nb + lane]      = __float2bfloat16(x0 - __bfloat162float(h0));
    xh[nb + lane + 32] = h1;
    xl[nb + lane + 32] = __float2bfloat16(x1 - __bfloat162float(h1));
}

// ---------------- mma.sync helpers ----------------
__device__ __forceinline__ void mma_bf16(float* c, uint32_t a0, uint32_t a1, uint32_t a2, uint32_t a3,
                                         uint32_t b0, uint32_t b1) {
    asm volatile("mma.sync.aligned.m16n8k16.row.col.f32.bf16.bf16.f32 "
                 "{%0,%1,%2,%3}, {%4,%5,%6,%7}, {%8,%9}, {%0,%1,%2,%3};"
                 : "+f"(c[0]), "+f"(c[1]), "+f"(c[2]), "+f"(c[3])
                 : "r"(a0), "r"(a1), "r"(a2), "r"(a3), "r"(b0), "r"(b1));
}

__device__ __forceinline__ void split_pack(float a, float b, uint32_t& hi, uint32_t& lo) {
    __nv_bfloat16 ha = __float2bfloat16(a), hb = __float2bfloat16(b);
    float ra = a - __bfloat162float(ha), rb = b - __bfloat162float(hb);
    hi = (uint32_t)__bfloat16_as_ushort(ha) | ((uint32_t)__bfloat16_as_ushort(hb) << 16);
    lo = (uint32_t)__bfloat16_as_ushort(__float2bfloat16(ra)) |
         ((uint32_t)__bfloat16_as_ushort(__float2bfloat16(rb)) << 16);
}

#define SP 136  // smem row stride (bf16)

template <int NT, int KST>
__device__ __forceinline__ void gemm_half(const __nv_bfloat16* Ah, const __nv_bfloat16* Al,
                                          const __nv_bfloat16* Bh, const __nv_bfloat16* Bl,
                                          int mb, int g, int tg, float (*acc)[4]) {
#pragma unroll
    for (int k = 0; k < KST; k++) {
        int k0 = k * 16 + tg * 2;
        uint32_t ah0 = *(const uint32_t*)(Ah + (mb + g) * SP + k0);
        uint32_t ah1 = *(const uint32_t*)(Ah + (mb + g + 8) * SP + k0);
        uint32_t ah2 = *(const uint32_t*)(Ah + (mb + g) * SP + k0 + 8);
        uint32_t ah3 = *(const uint32_t*)(Ah + (mb + g + 8) * SP + k0 + 8);
        uint32_t al0 = *(const uint32_t*)(Al + (mb + g) * SP + k0);
        uint32_t al1 = *(const uint32_t*)(Al + (mb + g + 8) * SP + k0);
        uint32_t al2 = *(const uint32_t*)(Al + (mb + g) * SP + k0 + 8);
        uint32_t al3 = *(const uint32_t*)(Al + (mb + g + 8) * SP + k0 + 8);
#pragma unroll
        for (int t = 0; t < NT; t++) {
            int nb = t * 8 + g;
            uint32_t bh0 = *(const uint32_t*)(Bh + nb * SP + k0);
            uint32_t bh1 = *(const uint32_t*)(Bh + nb * SP + k0 + 8);
            uint32_t bl0 = *(const uint32_t*)(Bl + nb * SP + k0);
            uint32_t bl1 = *(const uint32_t*)(Bl + nb * SP + k0 + 8);
            mma_bf16(acc[t], ah0, ah1, ah2, ah3, bh0, bh1);
            mma_bf16(acc[t], ah0, ah1, ah2, ah3, bl0, bl1);
            mma_bf16(acc[t], al0, al1, al2, al3, bh0, bh1);
        }
    }
}

template <int NT>
__device__ __forceinline__ void epi_relu_to_A(float (*acc)[4], const float* bias,
                                              __nv_bfloat16* Ah, __nv_bfloat16* Al,
                                              int mb, int g, int tg) {
    int r0 = mb + g, r1 = mb + g + 8;
#pragma unroll
    for (int t = 0; t < NT; t++) {
        int c0 = t * 8 + tg * 2;
        float b0 = __ldg(&bias[c0]), b1 = __ldg(&bias[c0 + 1]);
        uint32_t h, l;
        split_pack(fmaxf(acc[t][0] + b0, 0.f), fmaxf(acc[t][1] + b1, 0.f), h, l);
        *(uint32_t*)(Ah + r0 * SP + c0) = h;
        *(uint32_t*)(Al + r0 * SP + c0) = l;
        split_pack(fmaxf(acc[t][2] + b0, 0.f), fmaxf(acc[t][3] + b1, 0.f), h, l);
        *(uint32_t*)(Ah + r1 * SP + c0) = h;
        *(uint32_t*)(Al + r1 * SP + c0) = l;
    }
}

// ---------------- fused 3-layer MLP on tensor pipe, 2 CTAs/SM ----------------
// smem: Ah/Al [128][SP] + Bh/Bl [64][SP] bf16 = 104448 B.
template <int IN_F, int OUT_F, bool SCATTER, bool MASK, bool XSPLIT>
__global__ void __launch_bounds__(256, 2)
k_mlp3_tc(const float* __restrict__ X,
          const __nv_bfloat16* __restrict__ Xh, const __nv_bfloat16* __restrict__ Xl,
          int rows,
          const float* __restrict__ W0f, const __nv_bfloat16* __restrict__ w0t,
          const float* __restrict__ B0,
          const __nv_bfloat16* __restrict__ w1t, const float* __restrict__ B1,
          const __nv_bfloat16* __restrict__ w2t, const float* __restrict__ B2,
          float* __restrict__ out, const int* __restrict__ slot,
          const float* __restrict__ rawn) {
    extern __shared__ __nv_bfloat16 smb[];
    __nv_bfloat16* Ah = smb;
    __nv_bfloat16* Al = smb + 128 * SP;
    __nv_bfloat16* Bh = smb + 2 * 128 * SP;
    __nv_bfloat16* Bl = smb + (2 * 128 + 64) * SP;

    const int tid  = threadIdx.x;
    const int lane = tid & 31;
    const int wid  = tid >> 5;
    const int g    = lane >> 2;
    const int tg   = lane & 3;
    const int mb   = wid * 16;
    const int row0 = blockIdx.x * 128;

    float acc[16][4];

    // ================= layer 0 =================
    if (IN_F <= 4) {
        int row = tid & 127;
        int ch  = (tid >> 7) * 64;
        int gr  = row0 + row;
        float xv[IN_F];
#pragma unroll
        for (int i = 0; i < IN_F; i++)
            xv[i] = (gr < rows) ? __ldg(&X[(size_t)gr * IN_F + i]) : 0.f;
        uint32_t* ph = (uint32_t*)(Ah + row * SP + ch);
        uint32_t* pl = (uint32_t*)(Al + row * SP + ch);
#pragma unroll 4
        for (int j = 0; j < 32; j++) {
            int c = ch + 2 * j;
            float v0 = __ldg(&B0[c]), v1 = __ldg(&B0[c + 1]);
#pragma unroll
            for (int i = 0; i < IN_F; i++) {
                v0 += xv[i] * __ldg(&W0f[i * HF + c]);
                v1 += xv[i] * __ldg(&W0f[i * HF + c + 1]);
            }
            uint32_t h, l;
            split_pack(fmaxf(v0, 0.f), fmaxf(v1, 0.f), h, l);
            ph[j] = h;
            pl[j] = l;
        }
        __syncthreads();
    } else {
        if (XSPLIT) {
            const uint32_t* shp = (const uint32_t*)Xh + (size_t)row0 * 32;
            const uint32_t* slp = (const uint32_t*)Xl + (size_t)row0 * 32;
            for (int idx = tid; idx < 128 * 32; idx += 256) {
                int r = idx >> 5, w = idx & 31;
                ((uint32_t*)Ah)[r * 68 + w] = shp[idx];
                ((uint32_t*)Al)[r * 68 + w] = slp[idx];
            }
        } else {
            const float2* xs = (const float2*)(X + (size_t)row0 * 64);
            for (int idx = tid; idx < 128 * 32; idx += 256) {
                int r = idx >> 5, w = idx & 31;
                float2 v = __ldg(&xs[idx]);
                uint32_t h, l;
                split_pack(v.x, v.y, h, l);
                ((uint32_t*)Ah)[r * 68 + w] = h;
                ((uint32_t*)Al)[r * 68 + w] = l;
            }
        }
#pragma unroll
        for (int t = 0; t < 16; t++)
#pragma unroll
            for (int j = 0; j < 4; j++) acc[t][j] = 0.f;
        const uint32_t* s0 = (const uint32_t*)w0t;
#pragma unroll
        for (int nh = 0; nh < 2; nh++) {
            __syncthreads();
            for (int idx = tid; idx < 64 * 32; idx += 256) {
                int r = idx >> 5, w = idx & 31;
                ((uint32_t*)Bh)[r * 68 + w] = s0[(nh * 64 + r) * 32 + w];
                ((uint32_t*)Bl)[r * 68 + w] = s0[(nh * 64 + r) * 32 + w + 8192];
            }
            __syncthreads();
            gemm_half<8, 4>(Ah, Al, Bh, Bl, mb, g, tg, acc + nh * 8);
        }
        __syncthreads();
        epi_relu_to_A<16>(acc, B0, Ah, Al, mb, g, tg);
        __syncthreads();
    }

    // ================= layer 1 (128 -> 128), two 64-N halves =================
#pragma unroll
    for (int t = 0; t < 16; t++)
#pragma unroll
        for (int j = 0; j < 4; j++) acc[t][j] = 0.f;
    {
        const uint32_t* s1 = (const uint32_t*)w1t;
#pragma unroll
        for (int nh = 0; nh < 2; nh++) {
            if (nh) __syncthreads();
            for (int idx = tid; idx < 64 * 64; idx += 256) {
                int r = idx >> 6, w = idx & 63;
                ((uint32_t*)Bh)[r * 68 + w] = s1[(nh * 64 + r) * 64 + w];
                ((uint32_t*)Bl)[r * 68 + w] = s1[(nh * 64 + r) * 64 + w + 8192];
            }
            __syncthreads();
            gemm_half<8, 8>(Ah, Al, Bh, Bl, mb, g, tg, acc + nh * 8);
        }
    }
    __syncthreads();
    epi_relu_to_A<16>(acc, B1, Ah, Al, mb, g, tg);
    __syncthreads();

    // ================= layer 2 (128 -> OUT_F, linear) =================
    constexpr int NT2 = (OUT_F + 7) / 8;
    if (OUT_F % 8) {
        for (int idx = tid; idx < 8 * 68; idx += 256) {
            ((uint32_t*)Bh)[idx] = 0;
            ((uint32_t*)Bl)[idx] = 0;
        }
        __syncthreads();
    }
    {
        const uint32_t* s2 = (const uint32_t*)w2t;
        for (int idx = tid; idx < OUT_F * 64; idx += 256) {
            int r = idx >> 6, w = idx & 63;
            ((uint32_t*)Bh)[r * 68 + w] = s2[idx];
            ((uint32_t*)Bl)[r * 68 + w] = s2[idx + 8192];
        }
    }
    __syncthreads();
#pragma unroll
    for (int t = 0; t < NT2; t++)
#pragma unroll
        for (int j = 0; j < 4; j++) acc[t][j] = 0.f;
    gemm_half<NT2, 8>(Ah, Al, Bh, Bl, mb, g, tg, acc);

    // epilogue -> gmem
    {
        int r0g = row0 + mb + g;
        int r1g = r0g + 8;
        bool v0 = r0g < rows, v1 = r1g < rows;
        int o0 = 0, o1 = 0;
        float m0 = 1.f, m1 = 1.f;
        if (v0) {
            o0 = SCATTER ? __ldg(&slot[r0g]) : r0g;
            if (MASK)
                m0 = ((fabsf(rawn[(size_t)r0g * 2]) + fabsf(rawn[(size_t)r0g * 2 + 1])) != 0.f) ? 1.f : 0.f;
        }
        if (v1) {
            o1 = SCATTER ? __ldg(&slot[r1g]) : r1g;
            if (MASK)
                m1 = ((fabsf(rawn[(size_t)r1g * 2]) + fabsf(rawn[(size_t)r1g * 2 + 1])) != 0.f) ? 1.f : 0.f;
        }
#pragma unroll
        for (int t = 0; t < NT2; t++) {
            int c0 = t * 8 + tg * 2;
            if (c0 < OUT_F) {
                float b0 = __ldg(&B2[c0]), b1 = __ldg(&B2[c0 + 1]);
                if (v0) {
                    out[(size_t)o0 * OUT_F + c0]     = (acc[t][0] + b0) * m0;
                    out[(size_t)o0 * OUT_F + c0 + 1] = (acc[t][1] + b1) * m0;
                }
                if (v1) {
                    out[(size_t)o1 * OUT_F + c0]     = (acc[t][2] + b0) * m1;
                    out[(size_t)o1 * OUT_F + c0 + 1] = (acc[t][3] + b1) * m1;
                }
            }
        }
    }
}

static inline int ceilDiv(int a, int b) { return (a + b - 1) / b; }

extern "C" void kernel_launch(void* const* d_in, const int* in_sizes, int n_in,
                              void* d_out, int out_size) {
    (void)in_sizes; (void)n_in; (void)out_size;
    const float* nodes = (const float*)d_in[0];
    const float* edges = (const float*)d_in[1];
    const int*   send  = (const int*)d_in[2];
    const int*   recv  = (const int*)d_in[3];
    const float* enW0 = (const float*)d_in[4],  *enb0 = (const float*)d_in[5];
    const float* enW1 = (const float*)d_in[6],  *enb1 = (const float*)d_in[7];
    const float* enW2 = (const float*)d_in[8],  *enb2 = (const float*)d_in[9];
    const float* eeW0 = (const float*)d_in[10], *eeb0 = (const float*)d_in[11];
    const float* eeW1 = (const float*)d_in[12], *eeb1 = (const float*)d_in[13];
    const float* eeW2 = (const float*)d_in[14], *eeb2 = (const float*)d_in[15];
    const float* pW0  = (const float*)d_in[16], *pb0  = (const float*)d_in[17];
    const float* pW1  = (const float*)d_in[18], *pb1  = (const float*)d_in[19];
    const float* pW2  = (const float*)d_in[20], *pb2  = (const float*)d_in[21];
    const float* dW0  = (const float*)d_in[22], *db0  = (const float*)d_in[23];
    const float* dW1  = (const float*)d_in[24], *db1  = (const float*)d_in[25];
    const float* dW2  = (const float*)d_in[26], *db2  = (const float*)d_in[27];
    float* out = (float*)d_out;

    void *pe, *pn, *pxh, *pxl, *pwt, *pdeg, *poff, *psp, *pslot;
    cudaGetSymbolAddress(&pe, g_e);
    cudaGetSymbolAddress(&pn, g_n);
    cudaGetSymbolAddress(&pxh, g_xh);
    cudaGetSymbolAddress(&pxl, g_xl);
    cudaGetSymbolAddress(&pwt, g_wt);
    cudaGetSymbolAddress(&pdeg, g_deg);
    cudaGetSymbolAddress(&poff, g_off);
    cudaGetSymbolAddress(&psp, g_sperm);
    cudaGetSymbolAddress(&pslot, g_slot);
    const __nv_bfloat16* wt = (const __nv_bfloat16*)pwt;

    const int smemB = (2 * 128 + 2 * 64) * SP * 2;  // 104448
    cudaFuncSetAttribute(k_mlp3_tc<2, 64, false, false, false>, cudaFuncAttributeMaxDynamicSharedMemorySize, smemB);
    cudaFuncSetAttribute(k_mlp3_tc<3, 64, true,  false, false>, cudaFuncAttributeMaxDynamicSharedMemorySize, smemB);
    cudaFuncSetAttribute(k_mlp3_tc<64, 64, false, false, true>, cudaFuncAttributeMaxDynamicSharedMemorySize, smemB);
    cudaFuncSetAttribute(k_mlp3_tc<64, 2, false, true, false>,  cudaFuncAttributeMaxDynamicSharedMemorySize, smemB);

    // CSR build (by receiver)
    cudaMemsetAsync(pdeg, 0, NN * sizeof(int));
    k_hist<<<ceilDiv(EE, 256), 256>>>(recv);
    k_scan1<<<NB_SCAN, 256>>>();
    k_scan2<<<1, 256>>>();
    k_scan3<<<NB_SCAN, 256>>>();
    k_scatter<<<ceilDiv(EE, 256), 256>>>(recv, send);

    // weight prep
    WTable tb;
    tb.s[0] = {enW1, 128, 128};
    tb.s[1] = {enW2, 64, 128};
    tb.s[2] = {eeW1, 128, 128};
    tb.s[3] = {eeW2, 64, 128};
    for (int s = 0; s < 5; s++) {
        tb.s[4 + s]  = {pW0 + (size_t)s * 64 * 128,  128, 64};
        tb.s[9 + s]  = {pW1 + (size_t)s * 128 * 128, 128, 128};
        tb.s[14 + s] = {pW2 + (size_t)s * 128 * 64,  64, 128};
    }
    tb.s[19] = {dW0, 128, 64};
    tb.s[20] = {dW1, 128, 128};
    tb.s[21] = {dW2, 2, 128};
    k_prep<<<dim3(64, 22), 256>>>(tb);

    // encoders
    k_mlp3_tc<2, 64, false, false, false><<<ceilDiv(NN, 128), 256, smemB>>>(
        nodes, nullptr, nullptr, NN,
        enW0, wt + 0 * 32768, enb0, wt + 0 * 32768, enb1, wt + 1 * 32768, enb2,
        (float*)pn, nullptr, nullptr);
    k_mlp3_tc<3, 64, true, false, false><<<ceilDiv(EE, 128), 256, smemB>>>(
        edges, nullptr, nullptr, EE,
        eeW0, wt + 2 * 32768, eeb0, wt + 2 * 32768, eeb1, wt + 3 * 32768, eeb2,
        (float*)pe, (const int*)pslot, nullptr);

    // processor steps
    for (int s = 0; s < 5; s++) {
        k_agg<<<ceilDiv(NN * 32, 256), 256>>>(
            (const float*)pn, (const float*)pe, (const int*)psp, (const int*)poff,
            (__nv_bfloat16*)pxh, (__nv_bfloat16*)pxl);
        k_mlp3_tc<64, 64, false, false, true><<<ceilDiv(NN, 128), 256, smemB>>>(
            nullptr, (const __nv_bfloat16*)pxh, (const __nv_bfloat16*)pxl, NN,
            nullptr, wt + (size_t)(4 + s) * 32768, pb0 + (size_t)s * 128,
            wt + (size_t)(9 + s) * 32768, pb1 + (size_t)s * 128,
            wt + (size_t)(14 + s) * 32768, pb2 + (size_t)s * 64,
            (float*)pn, nullptr, nullptr);
    }

    // decoder + mask
    k_mlp3_tc<64, 2, false, true, false><<<ceilDiv(NN, 128), 256, smemB>>>(
        (const float*)pn, nullptr, nullptr, NN,
        nullptr, wt + 19 * 32768, db0, wt + 20 * 32768, db1, wt + 21 * 32768, db2,
        out, nullptr, nodes);
}

// round 15
// speedup vs baseline: 1.5924x; 1.0591x over previous
#include <cuda_runtime.h>
#include <cuda_bf16.h>
#include <cstdint>
#include <cstddef>

#define NN 50000
#define EE 1250000
#define LF 64
#define HF 128
#define EPSV 1e-6f
#define NB_SCAN 196   // ceil(50000/256)

// ---------------- static device scratch (no allocs allowed) ----------------
__device__ float g_e[(size_t)EE * LF];                 // edge latents (CSR order)
__device__ float g_n[(size_t)(NN + 128) * LF];         // node latents (padded)
__device__ __nv_bfloat16 g_xh[(size_t)(NN + 128) * LF];// processor input hi (padded)
__device__ __nv_bfloat16 g_xl[(size_t)(NN + 128) * LF];// processor input lo (padded)
__device__ __nv_bfloat16 g_wt[22 * 32768];             // weights: [N][K] bf16, hi then lo(+16384)
__device__ int g_deg[NN];
__device__ int g_off[NN + 1];
__device__ int g_cur[NN];
__device__ int g_bsum[NB_SCAN];
__device__ int g_slot[EE];
__device__ int g_sperm[EE];

__device__ __forceinline__ float ldcs_f(const float* p) {
    float v;
    asm volatile("ld.global.cs.f32 %0, [%1];" : "=f"(v) : "l"(p));
    return v;
}
__device__ __forceinline__ void stcs_f(float* p, float v) {
    asm volatile("st.global.cs.f32 [%0], %1;" :: "l"(p), "f"(v));
}

// ---------------- CSR build ----------------
__global__ void k_hist(const int* __restrict__ recv) {
    int i = blockIdx.x * blockDim.x + threadIdx.x;
    if (i < EE) atomicAdd(&g_deg[recv[i]], 1);
}

__global__ void k_scan1() {
    __shared__ int sh[256];
    int t = threadIdx.x;
    int i = blockIdx.x * 256 + t;
    int v = (i < NN) ? g_deg[i] : 0;
    sh[t] = v;
    __syncthreads();
#pragma unroll
    for (int d = 1; d < 256; d <<= 1) {
        int x = (t >= d) ? sh[t - d] : 0;
        __syncthreads();
        sh[t] += x;
        __syncthreads();
    }
    if (i < NN) g_off[i] = sh[t] - v;
    if (t == 255) g_bsum[blockIdx.x] = sh[255];
}

__global__ void k_scan2() {
    __shared__ int sh[256];
    int t = threadIdx.x;
    int v = (t < NB_SCAN) ? g_bsum[t] : 0;
    sh[t] = v;
    __syncthreads();
#pragma unroll
    for (int d = 1; d < 256; d <<= 1) {
        int x = (t >= d) ? sh[t - d] : 0;
        __syncthreads();
        sh[t] += x;
        __syncthreads();
    }
    if (t < NB_SCAN) g_bsum[t] = sh[t] - v;
}

__global__ void k_scan3() {
    int i = blockIdx.x * 256 + threadIdx.x;
    if (i < NN) {
        int o = g_off[i] + g_bsum[blockIdx.x];
        g_off[i] = o;
        g_cur[i] = o;
    }
    if (i == 0) g_off[NN] = EE;
}

__global__ void k_scatter(const int* __restrict__ recv, const int* __restrict__ send) {
    int i = blockIdx.x * blockDim.x + threadIdx.x;
    if (i < EE) {
        int p = atomicAdd(&g_cur[recv[i]], 1);
        g_slot[i] = p;
        g_sperm[p] = send[i];
    }
}

// ---------------- weight prep: fp32 [K][N] -> bf16 hi/lo [N][K] ----------------
struct WSlot { const float* src; int N; int K; };
struct WTable { WSlot s[22]; };

__global__ void k_prep(WTable tab) {
    int m = blockIdx.y;
    WSlot sl = tab.s[m];
    int total = sl.N * sl.K;
    int e = blockIdx.x * 256 + threadIdx.x;
    if (e >= total) return;
    int k = e / sl.N;
    int n = e - k * sl.N;
    float v = __ldg(&sl.src[e]);
    __nv_bfloat16 h = __float2bfloat16(v);
    __nv_bfloat16 l = __float2bfloat16(v - __bfloat162float(h));
    size_t off = (size_t)m * 32768 + (size_t)n * sl.K + k;
    g_wt[off] = h;
    g_wt[off + 16384] = l;
}

// ---------------- softmax aggregation: R7 structure + sp-prefetch + streaming e ----------------
__global__ void k_agg(const float* __restrict__ n, const float* __restrict__ e,
                      const int* __restrict__ sp, const int* __restrict__ off,
                      __nv_bfloat16* __restrict__ xh, __nv_bfloat16* __restrict__ xl) {
    int w = (blockIdx.x * blockDim.x + threadIdx.x) >> 5;
    int lane = threadIdx.x & 31;
    if (w >= NN) return;
    int p0 = __ldg(&off[w]);
    int p1 = __ldg(&off[w + 1]);

    const float NEG = -3.0e38f;
    float mxA0 = NEG, mxA1 = NEG, mxB0 = NEG, mxB1 = NEG;
    float saA0 = 0.f, sbA0 = 0.f, saA1 = 0.f, sbA1 = 0.f;
    float saB0 = 0.f, sbB0 = 0.f, saB1 = 0.f, sbB1 = 0.f;

    int p = p0;
    int sA = 0, sB = 0;
    if (p + 1 < p1) {
        sA = __ldg(&sp[p]);
        sB = __ldg(&sp[p + 1]);
    }
    while (p + 1 < p1) {
        int pn = p + 2;
        int sA2 = 0, sB2 = 0;
        if (pn + 1 < p1) {                 // prefetch next pair's indices
            sA2 = __ldg(&sp[pn]);
            sB2 = __ldg(&sp[pn + 1]);
        }
        size_t eA = (size_t)p * LF, eB = (size_t)(p + 1) * LF;
        size_t nA = (size_t)sA * LF, nB = (size_t)sB * LF;
        float mA0 = fmaxf(n[nA + lane]      + ldcs_f(e + eA + lane),      0.f) + EPSV;
        float mA1 = fmaxf(n[nA + lane + 32] + ldcs_f(e + eA + lane + 32), 0.f) + EPSV;
        float mB0 = fmaxf(n[nB + lane]      + ldcs_f(e + eB + lane),      0.f) + EPSV;
        float mB1 = fmaxf(n[nB + lane + 32] + ldcs_f(e + eB + lane + 32), 0.f) + EPSV;

        float nm, c, t;
        nm = fmaxf(mxA0, mA0); c = __expf(mxA0 - nm); t = __expf(mA0 - nm);
        saA0 = saA0 * c + t; sbA0 = sbA0 * c + t * mA0; mxA0 = nm;
        nm = fmaxf(mxA1, mA1); c = __expf(mxA1 - nm); t = __expf(mA1 - nm);
        saA1 = saA1 * c + t; sbA1 = sbA1 * c + t * mA1; mxA1 = nm;
        nm = fmaxf(mxB0, mB0); c = __expf(mxB0 - nm); t = __expf(mB0 - nm);
        saB0 = saB0 * c + t; sbB0 = sbB0 * c + t * mB0; mxB0 = nm;
        nm = fmaxf(mxB1, mB1); c = __expf(mxB1 - nm); t = __expf(mB1 - nm);
        saB1 = saB1 * c + t; sbB1 = sbB1 * c + t * mB1; mxB1 = nm;

        p = pn;
        sA = sA2;
        sB = sB2;
    }
    if (p < p1) {
        int sT = __ldg(&sp[p]);
        size_t eA = (size_t)p * LF, nA = (size_t)sT * LF;
        float mA0 = fmaxf(n[nA + lane]      + ldcs_f(e + eA + lane),      0.f) + EPSV;
        float mA1 = fmaxf(n[nA + lane + 32] + ldcs_f(e + eA + lane + 32), 0.f) + EPSV;
        float nm, c, t;
        nm = fmaxf(mxA0, mA0); c = __expf(mxA0 - nm); t = __expf(mA0 - nm);
        saA0 = saA0 * c + t; sbA0 = sbA0 * c + t * mA0; mxA0 = nm;
        nm = fmaxf(mxA1, mA1); c = __expf(mxA1 - nm); t = __expf(mA1 - nm);
        saA1 = saA1 * c + t; sbA1 = sbA1 * c + t * mA1; mxA1 = nm;
    }

    // merge streams (finite sentinel -> no NaN)
    float nm0 = fmaxf(mxA0, mxB0);
    float sa0 = saA0 * __expf(mxA0 - nm0) + saB0 * __expf(mxB0 - nm0);
    float sb0 = sbA0 * __expf(mxA0 - nm0) + sbB0 * __expf(mxB0 - nm0);
    float nm1 = fmaxf(mxA1, mxB1);
    float sa1 = saA1 * __expf(mxA1 - nm1) + saB1 * __expf(mxB1 - nm1);
    float sb1 = sbA1 * __expf(mxA1 - nm1) + sbB1 * __expf(mxB1 - nm1);

    float a0 = (sa0 > 0.f) ? sb0 / sa0 : 0.f;
    float a1 = (sa1 > 0.f) ? sb1 / sa1 : 0.f;
    size_t nb = (size_t)w * LF;
    float x0 = n[nb + lane]      + a0;
    float x1 = n[nb + lane + 32] + a1;
    __nv_bfloat16 h0 = __float2bfloat16(x0);
    __nv_bfloat16 h1 = __float2bfloat16(x1);
    xh[nb + lane]      = h0;
    xl[nb + lane]      = __float2bfloat16(x0 - __bfloat162float(h0));
    xh[nb + lane + 32] = h1;
    xl[nb + lane + 32] = __float2bfloat16(x1 - __bfloat162float(h1));
}

// ---------------- mma.sync helpers ----------------
__device__ __forceinline__ void mma_bf16(float* c, uint32_t a0, uint32_t a1, uint32_t a2, uint32_t a3,
                                         uint32_t b0, uint32_t b1) {
    asm volatile("mma.sync.aligned.m16n8k16.row.col.f32.bf16.bf16.f32 "
                 "{%0,%1,%2,%3}, {%4,%5,%6,%7}, {%8,%9}, {%0,%1,%2,%3};"
                 : "+f"(c[0]), "+f"(c[1]), "+f"(c[2]), "+f"(c[3])
                 : "r"(a0), "r"(a1), "r"(a2), "r"(a3), "r"(b0), "r"(b1));
}

__device__ __forceinline__ void split_pack(float a, float b, uint32_t& hi, uint32_t& lo) {
    __nv_bfloat16 ha = __float2bfloat16(a), hb = __float2bfloat16(b);
    float ra = a - __bfloat162float(ha), rb = b - __bfloat162float(hb);
    hi = (uint32_t)__bfloat16_as_ushort(ha) | ((uint32_t)__bfloat16_as_ushort(hb) << 16);
    lo = (uint32_t)__bfloat16_as_ushort(__float2bfloat16(ra)) |
         ((uint32_t)__bfloat16_as_ushort(__float2bfloat16(rb)) << 16);
}

#define SP 136  // smem row stride (bf16)

template <int NT, int KST>
__device__ __forceinline__ void gemm_half(const __nv_bfloat16* Ah, const __nv_bfloat16* Al,
                                          const __nv_bfloat16* Bh, const __nv_bfloat16* Bl,
                                          int mb, int g, int tg, float (*acc)[4]) {
#pragma unroll
    for (int k = 0; k < KST; k++) {
        int k0 = k * 16 + tg * 2;
        uint32_t ah0 = *(const uint32_t*)(Ah + (mb + g) * SP + k0);
        uint32_t ah1 = *(const uint32_t*)(Ah + (mb + g + 8) * SP + k0);
        uint32_t ah2 = *(const uint32_t*)(Ah + (mb + g) * SP + k0 + 8);
        uint32_t ah3 = *(const uint32_t*)(Ah + (mb + g + 8) * SP + k0 + 8);
        uint32_t al0 = *(const uint32_t*)(Al + (mb + g) * SP + k0);
        uint32_t al1 = *(const uint32_t*)(Al + (mb + g + 8) * SP + k0);
        uint32_t al2 = *(const uint32_t*)(Al + (mb + g) * SP + k0 + 8);
        uint32_t al3 = *(const uint32_t*)(Al + (mb + g + 8) * SP + k0 + 8);
#pragma unroll
        for (int t = 0; t < NT; t++) {
            int nb = t * 8 + g;
            uint32_t bh0 = *(const uint32_t*)(Bh + nb * SP + k0);
            uint32_t bh1 = *(const uint32_t*)(Bh + nb * SP + k0 + 8);
            uint32_t bl0 = *(const uint32_t*)(Bl + nb * SP + k0);
            uint32_t bl1 = *(const uint32_t*)(Bl + nb * SP + k0 + 8);
            mma_bf16(acc[t], ah0, ah1, ah2, ah3, bh0, bh1);
            mma_bf16(acc[t], ah0, ah1, ah2, ah3, bl0, bl1);
            mma_bf16(acc[t], al0, al1, al2, al3, bh0, bh1);
        }
    }
}

template <int NT>
__device__ __forceinline__ void epi_relu_to_A(float (*acc)[4], const float* bias,
                                              __nv_bfloat16* Ah, __nv_bfloat16* Al,
                                              int mb, int g, int tg) {
    int r0 = mb + g, r1 = mb + g + 8;
#pragma unroll
    for (int t = 0; t < NT; t++) {
        int c0 = t * 8 + tg * 2;
        float b0 = __ldg(&bias[c0]), b1 = __ldg(&bias[c0 + 1]);
        uint32_t h, l;
        split_pack(fmaxf(acc[t][0] + b0, 0.f), fmaxf(acc[t][1] + b1, 0.f), h, l);
        *(uint32_t*)(Ah + r0 * SP + c0) = h;
        *(uint32_t*)(Al + r0 * SP + c0) = l;
        split_pack(fmaxf(acc[t][2] + b0, 0.f), fmaxf(acc[t][3] + b1, 0.f), h, l);
        *(uint32_t*)(Ah + r1 * SP + c0) = h;
        *(uint32_t*)(Al + r1 * SP + c0) = l;
    }
}

// ---------------- fused 3-layer MLP on tensor pipe, 2 CTAs/SM ----------------
// smem: Ah/Al [128][SP] + Bh/Bl [64][SP] bf16 = 104448 B.
template <int IN_F, int OUT_F, bool SCATTER, bool MASK, bool XSPLIT>
__global__ void __launch_bounds__(256, 2)
k_mlp3_tc(const float* __restrict__ X,
          const __nv_bfloat16* __restrict__ Xh, const __nv_bfloat16* __restrict__ Xl,
          int rows,
          const float* __restrict__ W0f, const __nv_bfloat16* __restrict__ w0t,
          const float* __restrict__ B0,
          const __nv_bfloat16* __restrict__ w1t, const float* __restrict__ B1,
          const __nv_bfloat16* __restrict__ w2t, const float* __restrict__ B2,
          float* __restrict__ out, const int* __restrict__ slot,
          const float* __restrict__ rawn) {
    extern __shared__ __nv_bfloat16 smb[];
    __nv_bfloat16* Ah = smb;
    __nv_bfloat16* Al = smb + 128 * SP;
    __nv_bfloat16* Bh = smb + 2 * 128 * SP;
    __nv_bfloat16* Bl = smb + (2 * 128 + 64) * SP;

    const int tid  = threadIdx.x;
    const int lane = tid & 31;
    const int wid  = tid >> 5;
    const int g    = lane >> 2;
    const int tg   = lane & 3;
    const int mb   = wid * 16;
    const int row0 = blockIdx.x * 128;

    float acc[16][4];

    // ================= layer 0 =================
    if (IN_F <= 4) {
        // stage W0 (IN_F x 128) + B0 (128) into smem once (Bh region, dead until L1)
        float* Wst = (float*)Bh;
        for (int idx = tid; idx < IN_F * HF; idx += 256) Wst[idx] = __ldg(&W0f[idx]);
        for (int idx = tid; idx < HF; idx += 256) Wst[IN_F * HF + idx] = __ldg(&B0[idx]);
        __syncthreads();

        int row = tid & 127;
        int ch  = (tid >> 7) * 64;
        int gr  = row0 + row;
        float xv[IN_F];
#pragma unroll
        for (int i = 0; i < IN_F; i++)
            xv[i] = (gr < rows) ? (SCATTER ? ldcs_f(&X[(size_t)gr * IN_F + i])
                                           : __ldg(&X[(size_t)gr * IN_F + i])) : 0.f;
        uint32_t* ph = (uint32_t*)(Ah + row * SP + ch);
        uint32_t* pl = (uint32_t*)(Al + row * SP + ch);
#pragma unroll 4
        for (int j = 0; j < 32; j++) {
            int c = ch + 2 * j;
            float v0 = Wst[IN_F * HF + c], v1 = Wst[IN_F * HF + c + 1];
#pragma unroll
            for (int i = 0; i < IN_F; i++) {
                v0 += xv[i] * Wst[i * HF + c];
                v1 += xv[i] * Wst[i * HF + c + 1];
            }
            uint32_t h, l;
            split_pack(fmaxf(v0, 0.f), fmaxf(v1, 0.f), h, l);
            ph[j] = h;
            pl[j] = l;
        }
        __syncthreads();
    } else {
        if (XSPLIT) {
            const uint32_t* shp = (const uint32_t*)Xh + (size_t)row0 * 32;
            const uint32_t* slp = (const uint32_t*)Xl + (size_t)row0 * 32;
            for (int idx = tid; idx < 128 * 32; idx += 256) {
                int r = idx >> 5, w = idx & 31;
                ((uint32_t*)Ah)[r * 68 + w] = shp[idx];
                ((uint32_t*)Al)[r * 68 + w] = slp[idx];
            }
        } else {
            const float2* xs = (const float2*)(X + (size_t)row0 * 64);
            for (int idx = tid; idx < 128 * 32; idx += 256) {
                int r = idx >> 5, w = idx & 31;
                float2 v = __ldg(&xs[idx]);
                uint32_t h, l;
                split_pack(v.x, v.y, h, l);
                ((uint32_t*)Ah)[r * 68 + w] = h;
                ((uint32_t*)Al)[r * 68 + w] = l;
            }
        }
#pragma unroll
        for (int t = 0; t < 16; t++)
#pragma unroll
            for (int j = 0; j < 4; j++) acc[t][j] = 0.f;
        const uint32_t* s0 = (const uint32_t*)w0t;
#pragma unroll
        for (int nh = 0; nh < 2; nh++) {
            __syncthreads();
            for (int idx = tid; idx < 64 * 32; idx += 256) {
                int r = idx >> 5, w = idx & 31;
                ((uint32_t*)Bh)[r * 68 + w] = s0[(nh * 64 + r) * 32 + w];
                ((uint32_t*)Bl)[r * 68 + w] = s0[(nh * 64 + r) * 32 + w + 8192];
            }
            __syncthreads();
            gemm_half<8, 4>(Ah, Al, Bh, Bl, mb, g, tg, acc + nh * 8);
        }
        __syncthreads();
        epi_relu_to_A<16>(acc, B0, Ah, Al, mb, g, tg);
        __syncthreads();
    }

    // ================= layer 1 (128 -> 128), two 64-N halves =================
#pragma unroll
    for (int t = 0; t < 16; t++)
#pragma unroll
        for (int j = 0; j < 4; j++) acc[t][j] = 0.f;
    {
        const uint32_t* s1 = (const uint32_t*)w1t;
#pragma unroll
        for (int nh = 0; nh < 2; nh++) {
            if (nh) __syncthreads();
            for (int idx = tid; idx < 64 * 64; idx += 256) {
                int r = idx >> 6, w = idx & 63;
                ((uint32_t*)Bh)[r * 68 + w] = s1[(nh * 64 + r) * 64 + w];
                ((uint32_t*)Bl)[r * 68 + w] = s1[(nh * 64 + r) * 64 + w + 8192];
            }
            __syncthreads();
            gemm_half<8, 8>(Ah, Al, Bh, Bl, mb, g, tg, acc + nh * 8);
        }
    }
    __syncthreads();
    epi_relu_to_A<16>(acc, B1, Ah, Al, mb, g, tg);
    __syncthreads();

    // ================= layer 2 (128 -> OUT_F, linear) =================
    constexpr int NT2 = (OUT_F + 7) / 8;
    if (OUT_F % 8) {
        for (int idx = tid; idx < 8 * 68; idx += 256) {
            ((uint32_t*)Bh)[idx] = 0;
            ((uint32_t*)Bl)[idx] = 0;
        }
        __syncthreads();
    }
    {
        const uint32_t* s2 = (const uint32_t*)w2t;
        for (int idx = tid; idx < OUT_F * 64; idx += 256) {
            int r = idx >> 6, w = idx & 63;
            ((uint32_t*)Bh)[r * 68 + w] = s2[idx];
            ((uint32_t*)Bl)[r * 68 + w] = s2[idx + 8192];
        }
    }
    __syncthreads();
#pragma unroll
    for (int t = 0; t < NT2; t++)
#pragma unroll
        for (int j = 0; j < 4; j++) acc[t][j] = 0.f;
    gemm_half<NT2, 8>(Ah, Al, Bh, Bl, mb, g, tg, acc);

    // epilogue -> gmem
    {
        int r0g = row0 + mb + g;
        int r1g = r0g + 8;
        bool v0 = r0g < rows, v1 = r1g < rows;
        int o0 = 0, o1 = 0;
        float m0 = 1.f, m1 = 1.f;
        if (v0) {
            o0 = SCATTER ? __ldg(&slot[r0g]) : r0g;
            if (MASK)
                m0 = ((fabsf(rawn[(size_t)r0g * 2]) + fabsf(rawn[(size_t)r0g * 2 + 1])) != 0.f) ? 1.f : 0.f;
        }
        if (v1) {
            o1 = SCATTER ? __ldg(&slot[r1g]) : r1g;
            if (MASK)
                m1 = ((fabsf(rawn[(size_t)r1g * 2]) + fabsf(rawn[(size_t)r1g * 2 + 1])) != 0.f) ? 1.f : 0.f;
        }
#pragma unroll
        for (int t = 0; t < NT2; t++) {
            int c0 = t * 8 + tg * 2;
            if (c0 < OUT_F) {
                float b0 = __ldg(&B2[c0]), b1 = __ldg(&B2[c0 + 1]);
                if (SCATTER) {
                    if (v0) {
                        stcs_f(&out[(size_t)o0 * OUT_F + c0],     (acc[t][0] + b0) * m0);
                        stcs_f(&out[(size_t)o0 * OUT_F + c0 + 1], (acc[t][1] + b1) * m0);
                    }
                    if (v1) {
                        stcs_f(&out[(size_t)o1 * OUT_F + c0],     (acc[t][2] + b0) * m1);
                        stcs_f(&out[(size_t)o1 * OUT_F + c0 + 1], (acc[t][3] + b1) * m1);
                    }
                } else {
                    if (v0) {
                        out[(size_t)o0 * OUT_F + c0]     = (acc[t][0] + b0) * m0;
                        out[(size_t)o0 * OUT_F + c0 + 1] = (acc[t][1] + b1) * m0;
                    }
                    if (v1) {
                        out[(size_t)o1 * OUT_F + c0]     = (acc[t][2] + b0) * m1;
                        out[(size_t)o1 * OUT_F + c0 + 1] = (acc[t][3] + b1) * m1;
                    }
                }
            }
        }
    }
}

static inline int ceilDiv(int a, int b) { return (a + b - 1) / b; }

extern "C" void kernel_launch(void* const* d_in, const int* in_sizes, int n_in,
                              void* d_out, int out_size) {
    (void)in_sizes; (void)n_in; (void)out_size;
    const float* nodes = (const float*)d_in[0];
    const float* edges = (const float*)d_in[1];
    const int*   send  = (const int*)d_in[2];
    const int*   recv  = (const int*)d_in[3];
    const float* enW0 = (const float*)d_in[4],  *enb0 = (const float*)d_in[5];
    const float* enW1 = (const float*)d_in[6],  *enb1 = (const float*)d_in[7];
    const float* enW2 = (const float*)d_in[8],  *enb2 = (const float*)d_in[9];
    const float* eeW0 = (const float*)d_in[10], *eeb0 = (const float*)d_in[11];
    const float* eeW1 = (const float*)d_in[12], *eeb1 = (const float*)d_in[13];
    const float* eeW2 = (const float*)d_in[14], *eeb2 = (const float*)d_in[15];
    const float* pW0  = (const float*)d_in[16], *pb0  = (const float*)d_in[17];
    const float* pW1  = (const float*)d_in[18], *pb1  = (const float*)d_in[19];
    const float* pW2  = (const float*)d_in[20], *pb2  = (const float*)d_in[21];
    const float* dW0  = (const float*)d_in[22], *db0  = (const float*)d_in[23];
    const float* dW1  = (const float*)d_in[24], *db1  = (const float*)d_in[25];
    const float* dW2  = (const float*)d_in[26], *db2  = (const float*)d_in[27];
    float* out = (float*)d_out;

    void *pe, *pn, *pxh, *pxl, *pwt, *pdeg, *poff, *psp, *pslot;
    cudaGetSymbolAddress(&pe, g_e);
    cudaGetSymbolAddress(&pn, g_n);
    cudaGetSymbolAddress(&pxh, g_xh);
    cudaGetSymbolAddress(&pxl, g_xl);
    cudaGetSymbolAddress(&pwt, g_wt);
    cudaGetSymbolAddress(&pdeg, g_deg);
    cudaGetSymbolAddress(&poff, g_off);
    cudaGetSymbolAddress(&psp, g_sperm);
    cudaGetSymbolAddress(&pslot, g_slot);
    const __nv_bfloat16* wt = (const __nv_bfloat16*)pwt;

    const int smemB = (2 * 128 + 2 * 64) * SP * 2;  // 104448
    cudaFuncSetAttribute(k_mlp3_tc<2, 64, false, false, false>, cudaFuncAttributeMaxDynamicSharedMemorySize, smemB);
    cudaFuncSetAttribute(k_mlp3_tc<3, 64, true,  false, false>, cudaFuncAttributeMaxDynamicSharedMemorySize, smemB);
    cudaFuncSetAttribute(k_mlp3_tc<64, 64, false, false, true>, cudaFuncAttributeMaxDynamicSharedMemorySize, smemB);
    cudaFuncSetAttribute(k_mlp3_tc<64, 2, false, true, false>,  cudaFuncAttributeMaxDynamicSharedMemorySize, smemB);

    // CSR build (by receiver)
    cudaMemsetAsync(pdeg, 0, NN * sizeof(int));
    k_hist<<<ceilDiv(EE, 256), 256>>>(recv);
    k_scan1<<<NB_SCAN, 256>>>();
    k_scan2<<<1, 256>>>();
    k_scan3<<<NB_SCAN, 256>>>();
    k_scatter<<<ceilDiv(EE, 256), 256>>>(recv, send);

    // weight prep
    WTable tb;
    tb.s[0] = {enW1, 128, 128};
    tb.s[1] = {enW2, 64, 128};
    tb.s[2] = {eeW1, 128, 128};
    tb.s[3] = {eeW2, 64, 128};
    for (int s = 0; s < 5; s++) {
        tb.s[4 + s]  = {pW0 + (size_t)s * 64 * 128,  128, 64};
        tb.s[9 + s]  = {pW1 + (size_t)s * 128 * 128, 128, 128};
        tb.s[14 + s] = {pW2 + (size_t)s * 128 * 64,  64, 128};
    }
    tb.s[19] = {dW0, 128, 64};
    tb.s[20] = {dW1, 128, 128};
    tb.s[21] = {dW2, 2, 128};
    k_prep<<<dim3(64, 22), 256>>>(tb);

    // encoders
    k_mlp3_tc<2, 64, false, false, false><<<ceilDiv(NN, 128), 256, smemB>>>(
        nodes, nullptr, nullptr, NN,
        enW0, wt + 0 * 32768, enb0, wt + 0 * 32768, enb1, wt + 1 * 32768, enb2,
        (float*)pn, nullptr, nullptr);
    k_mlp3_tc<3, 64, true, false, false><<<ceilDiv(EE, 128), 256, smemB>>>(
        edges, nullptr, nullptr, EE,
        eeW0, wt + 2 * 32768, eeb0, wt + 2 * 32768, eeb1, wt + 3 * 32768, eeb2,
        (float*)pe, (const int*)pslot, nullptr);

    // processor steps
    for (int s = 0; s < 5; s++) {
        k_agg<<<ceilDiv(NN * 32, 256), 256>>>(
            (const float*)pn, (const float*)pe, (const int*)psp, (const int*)poff,
            (__nv_bfloat16*)pxh, (__nv_bfloat16*)pxl);
        k_mlp3_tc<64, 64, false, false, true><<<ceilDiv(NN, 128), 256, smemB>>>(
            nullptr, (const __nv_bfloat16*)pxh, (const __nv_bfloat16*)pxl, NN,
            nullptr, wt + (size_t)(4 + s) * 32768, pb0 + (size_t)s * 128,
            wt + (size_t)(9 + s) * 32768, pb1 + (size_t)s * 128,
            wt + (size_t)(14 + s) * 32768, pb2 + (size_t)s * 64,
            (float*)pn, nullptr, nullptr);
    }

    // decoder + mask
    k_mlp3_tc<64, 2, false, true, false><<<ceilDiv(NN, 128), 256, smemB>>>(
        (const float*)pn, nullptr, nullptr, NN,
        nullptr, wt + 19 * 32768, db0, wt + 20 * 32768, db1, wt + 21 * 32768, db2,
        out, nullptr, nodes);
}